// round 1
// baseline (speedup 1.0000x reference)
#include <cuda_runtime.h>
#include <cstdint>
#include <cstddef>

// Problem constants
static constexpr int BATCH = 32;
static constexpr int NVERT = 5023;
static constexpr int SP    = 9;

// ---------------------------------------------------------------------------
// Scratch: __device__ globals (no cudaMalloc allowed anywhere).
// Intermediates h1..h4 (layout [B][N][C]) + transposed weights Wt[k][o].
// ---------------------------------------------------------------------------
__device__ float g_h1[(size_t)BATCH * NVERT * 32];
__device__ float g_h2[(size_t)BATCH * NVERT * 64];
__device__ float g_h3[(size_t)BATCH * NVERT * 128];
__device__ float g_h4[(size_t)BATCH * NVERT * 128];
__device__ float g_wt0[27 * 32];
__device__ float g_wt1[288 * 64];
__device__ float g_wt2[576 * 128];
__device__ float g_wt3[1152 * 128];
__device__ float g_wtl[128 * 256];

// ---------------------------------------------------------------------------
// Tiny weight transpose: Wt[k*OC + o] = W[o*K + k]
// ---------------------------------------------------------------------------
__global__ void transpose_w(const float* __restrict__ W, float* __restrict__ Wt,
                            int K, int OC) {
    int t = blockIdx.x * blockDim.x + threadIdx.x;
    if (t < K * OC) {
        int k = t / OC;
        int o = t - k * OC;
        Wt[t] = W[o * K + k];
    }
}

// ---------------------------------------------------------------------------
// Fused gather + GEMM layer.
//   rows  = ROWS per block = VT vertices x 32 batches (r = vt*32 + b)
//   cols  = OUT_C (whole output channel dim per block)
//   K     = SPIRAL * IN_C, processed in KC-wide chunks
// Register tile TM x TN per thread. A-frag reads are warp-broadcast scalars;
// W-frag reads are contiguous float4 from a K-major smem tile.
// ---------------------------------------------------------------------------
template<int IN_C, int OUT_C, int KC, int ROWS, int TM, int TN, bool GATHER, int SPIRAL>
__global__ void __launch_bounds__((OUT_C / TN) * (ROWS / TM))
layer_kernel(const float* __restrict__ hin,
             const int*   __restrict__ sidx_g,   // [NVERT][SPIRAL] for this layer
             const float* __restrict__ Wt,       // [K][OUT_C] transposed weights
             const float* __restrict__ bias,     // [OUT_C]
             float*       __restrict__ hout)     // [B][NVERT][OUT_C]
{
    constexpr int VT = ROWS / BATCH;
    constexpr int TX = OUT_C / TN;
    constexpr int TY = ROWS / TM;
    constexpr int NT = TX * TY;
    constexpr int K  = (GATHER ? SPIRAL : 1) * IN_C;
    constexpr int NCHUNK = K / KC;
    constexpr int AS = KC + 1;                   // padded A stride

    extern __shared__ float smem[];
    float* Asm = smem;                           // ROWS * AS
    float* Wsm = smem + ROWS * AS;               // KC * OUT_C
    int*   sidx = (int*)(Wsm + KC * OUT_C);      // VT * SPIRAL

    const int tid = threadIdx.x;
    const int tx  = tid % TX;
    const int ty  = tid / TX;
    const int v0  = blockIdx.x * VT;

    if constexpr (GATHER) {
        if (tid < VT * SPIRAL) {
            int vt = tid / SPIRAL;
            int s  = tid - vt * SPIRAL;
            int v  = v0 + vt;
            if (v >= NVERT) v = NVERT - 1;
            sidx[tid] = sidx_g[v * SPIRAL + s];
        }
        __syncthreads();
    }

    float acc[TM][TN];
#pragma unroll
    for (int i = 0; i < TM; ++i)
#pragma unroll
        for (int j = 0; j < TN; ++j) acc[i][j] = 0.f;

    for (int ch = 0; ch < NCHUNK; ++ch) {
        // ---- load W chunk (coalesced, conflict-free: already K-major) ----
        {
            const float4* wsrc = (const float4*)(Wt + (size_t)ch * KC * OUT_C);
            float4* wdst = (float4*)Wsm;
            for (int t = tid; t < KC * OUT_C / 4; t += NT) wdst[t] = wsrc[t];
        }
        // ---- gather A chunk ----
        if constexpr ((IN_C % KC) == 0) {
            // chunk lies within a single spiral slot s
            constexpr int PER_S = IN_C / KC;
            const int s  = GATHER ? (ch / PER_S) : 0;
            const int c0 = (ch % PER_S) * KC;
            constexpr int C4 = KC / 4;
            for (int t = tid; t < ROWS * C4; t += NT) {
                int r  = t / C4;
                int c4 = t - r * C4;
                int vt = r >> 5, b = r & 31;
                int v  = v0 + vt;
                if (v >= NVERT) v = NVERT - 1;
                int srow = GATHER ? sidx[vt * SPIRAL + s] : v;
                float4 val = *(const float4*)(hin + ((size_t)b * NVERT + srow) * IN_C + c0 + 4 * c4);
                float* dst = Asm + r * AS + 4 * c4;
                dst[0] = val.x; dst[1] = val.y; dst[2] = val.z; dst[3] = val.w;
            }
        } else {
            // generic elementwise gather (only L0: IN_C=3, KC=27)
            for (int t = tid; t < ROWS * KC; t += NT) {
                int r  = t / KC;
                int kk = t - r * KC;
                int vt = r >> 5, b = r & 31;
                int v  = v0 + vt;
                if (v >= NVERT) v = NVERT - 1;
                int kg = ch * KC + kk;
                int s  = kg / IN_C;
                int c  = kg - s * IN_C;
                int srow = GATHER ? sidx[vt * SPIRAL + s] : v;
                Asm[r * AS + kk] = hin[((size_t)b * NVERT + srow) * IN_C + c];
            }
        }
        __syncthreads();

        // ---- FMA mainloop ----
#pragma unroll 4
        for (int k = 0; k < KC; ++k) {
            float a[TM];
#pragma unroll
            for (int i = 0; i < TM; ++i) a[i] = Asm[(ty * TM + i) * AS + k];
            float w[TN];
#pragma unroll
            for (int j4 = 0; j4 < TN / 4; ++j4) {
                float4 wv = *(const float4*)(Wsm + k * OUT_C + tx * TN + 4 * j4);
                w[4 * j4 + 0] = wv.x; w[4 * j4 + 1] = wv.y;
                w[4 * j4 + 2] = wv.z; w[4 * j4 + 3] = wv.w;
            }
#pragma unroll
            for (int i = 0; i < TM; ++i)
#pragma unroll
                for (int j = 0; j < TN; ++j)
                    acc[i][j] += a[i] * w[j];
        }
        __syncthreads();
    }

    // ---- epilogue: bias + store ----
#pragma unroll
    for (int i = 0; i < TM; ++i) {
        int r  = ty * TM + i;
        int vt = r >> 5, b = r & 31;
        int v  = v0 + vt;
        if (v < NVERT) {
            float* dst = hout + ((size_t)b * NVERT + v) * OUT_C + tx * TN;
#pragma unroll
            for (int j = 0; j < TN; ++j) dst[j] = acc[i][j] + __ldg(&bias[tx * TN + j]);
        }
    }
}

// host-side smem size helper
static constexpr int smem_bytes(int ROWS, int KC, int OUT_C, int VT, int SPIRAL) {
    return (ROWS * (KC + 1) + KC * OUT_C) * 4 + VT * SPIRAL * 4;
}

extern "C" void kernel_launch(void* const* d_in, const int* in_sizes, int n_in,
                              void* d_out, int out_size) {
    const float* x  = (const float*)d_in[0];
    const int*   sp = (const int*)  d_in[1];
    const float* W0 = (const float*)d_in[2];
    const float* b0 = (const float*)d_in[3];
    const float* W1 = (const float*)d_in[4];
    const float* b1 = (const float*)d_in[5];
    const float* W2 = (const float*)d_in[6];
    const float* b2 = (const float*)d_in[7];
    const float* W3 = (const float*)d_in[8];
    const float* b3 = (const float*)d_in[9];
    const float* Wl = (const float*)d_in[10];
    const float* bl = (const float*)d_in[11];
    float* out = (float*)d_out;

    float *h1, *h2, *h3, *h4, *wt0, *wt1, *wt2, *wt3, *wtl;
    cudaGetSymbolAddress((void**)&h1,  g_h1);
    cudaGetSymbolAddress((void**)&h2,  g_h2);
    cudaGetSymbolAddress((void**)&h3,  g_h3);
    cudaGetSymbolAddress((void**)&h4,  g_h4);
    cudaGetSymbolAddress((void**)&wt0, g_wt0);
    cudaGetSymbolAddress((void**)&wt1, g_wt1);
    cudaGetSymbolAddress((void**)&wt2, g_wt2);
    cudaGetSymbolAddress((void**)&wt3, g_wt3);
    cudaGetSymbolAddress((void**)&wtl, g_wtl);

    // ---- weight transposes (tiny) ----
    auto T = [](const float* W, float* Wt, int K, int OC) {
        int n = K * OC;
        transpose_w<<<(n + 255) / 256, 256>>>(W, Wt, K, OC);
    };
    T(W0, wt0, 27, 32);
    T(W1, wt1, 288, 64);
    T(W2, wt2, 576, 128);
    T(W3, wt3, 1152, 128);
    T(Wl, wtl, 128, 256);

    const int* sp0 = sp + 0 * NVERT * SP;
    const int* sp1 = sp + 1 * NVERT * SP;
    const int* sp2 = sp + 2 * NVERT * SP;
    const int* sp3 = sp + 3 * NVERT * SP;

    // grid for ROWS=128 (4 verts/block) and ROWS=64 (2 verts/block)
    const int grid4 = (NVERT + 3) / 4;   // 1256
    const int grid2 = (NVERT + 1) / 2;   // 2512

    // ---- Layer 0: 3 -> 32 ----
    {
        auto k = layer_kernel<3, 32, 27, 128, 8, 4, true, 9>;
        constexpr int sm = smem_bytes(128, 27, 32, 4, 9);
        k<<<grid4, 8 * 16, sm>>>(x, sp0, wt0, b0, h1);
    }
    // ---- Layer 1: 32 -> 64 ----
    {
        auto k = layer_kernel<32, 64, 32, 128, 8, 8, true, 9>;
        constexpr int sm = smem_bytes(128, 32, 64, 4, 9);
        k<<<grid4, 8 * 16, sm>>>(h1, sp1, wt1, b1, h2);
    }
    // ---- Layer 2: 64 -> 128 ----
    {
        auto k = layer_kernel<64, 128, 64, 128, 8, 8, true, 9>;
        constexpr int sm = smem_bytes(128, 64, 128, 4, 9);   // ~66 KB
        cudaFuncSetAttribute((const void*)k, cudaFuncAttributeMaxDynamicSharedMemorySize, sm);
        k<<<grid4, 16 * 16, sm>>>(h2, sp2, wt2, b2, h3);
    }
    // ---- Layer 3: 128 -> 128 ----
    {
        auto k = layer_kernel<128, 128, 64, 128, 8, 8, true, 9>;
        constexpr int sm = smem_bytes(128, 64, 128, 4, 9);   // ~66 KB
        cudaFuncSetAttribute((const void*)k, cudaFuncAttributeMaxDynamicSharedMemorySize, sm);
        k<<<grid4, 16 * 16, sm>>>(h3, sp3, wt3, b3, h4);
    }
    // ---- Final linear: 128 -> 256 (no gather) ----
    {
        auto k = layer_kernel<128, 256, 64, 64, 8, 8, false, 1>;
        constexpr int sm = smem_bytes(64, 64, 256, 2, 1);    // ~82 KB
        cudaFuncSetAttribute((const void*)k, cudaFuncAttributeMaxDynamicSharedMemorySize, sm);
        k<<<grid2, 32 * 8, sm>>>(h4, nullptr, wtl, bl, out);
    }
}

// round 4
// speedup vs baseline: 2.6913x; 2.6913x over previous
#include <cuda_runtime.h>
#include <cuda_bf16.h>
#include <cstdint>
#include <cstddef>

static constexpr int BATCH = 32;
static constexpr int NVERT = 5023;
static constexpr int SP    = 9;

// ---------------------------------------------------------------------------
// Helpers (sm_100 base target: mma.sync + ldmatrix + cp.async only)
// ---------------------------------------------------------------------------
__device__ __forceinline__ uint32_t smem_u32(const void* p) {
    uint32_t a;
    asm("{ .reg .u64 t; cvta.to.shared.u64 t, %1; cvt.u32.u64 %0, t; }" : "=r"(a) : "l"(p));
    return a;
}
__device__ __forceinline__ void cp16(uint32_t dst, const void* src, int srcbytes) {
    asm volatile("cp.async.ca.shared.global [%0], [%1], 16, %2;"
                 :: "r"(dst), "l"(src), "r"(srcbytes));
}
__device__ __forceinline__ void cp_commit() {
    asm volatile("cp.async.commit_group;" ::: "memory");
}
__device__ __forceinline__ void cp_wait0() {
    asm volatile("cp.async.wait_group 0;" ::: "memory");
}
__device__ __forceinline__ void cp_wait1() {
    asm volatile("cp.async.wait_group 1;" ::: "memory");
}
__device__ __forceinline__ void ldm4(uint32_t addr, uint32_t* r) {
    asm volatile("ldmatrix.sync.aligned.m8n8.x4.shared.b16 {%0,%1,%2,%3}, [%4];"
                 : "=r"(r[0]), "=r"(r[1]), "=r"(r[2]), "=r"(r[3]) : "r"(addr));
}
__device__ __forceinline__ void mma16816(float* d, const uint32_t* a, const uint32_t* b) {
    asm volatile("mma.sync.aligned.m16n8k16.row.col.f32.bf16.bf16.f32 "
                 "{%0,%1,%2,%3}, {%4,%5,%6,%7}, {%8,%9}, {%0,%1,%2,%3};"
                 : "+f"(d[0]), "+f"(d[1]), "+f"(d[2]), "+f"(d[3])
                 : "r"(a[0]), "r"(a[1]), "r"(a[2]), "r"(a[3]), "r"(b[0]), "r"(b[1]));
}
__device__ __forceinline__ uint32_t swz(uint32_t off) { return off ^ ((off >> 3) & 0x70); }

// ---------------------------------------------------------------------------
// Device global scratch
// ---------------------------------------------------------------------------
__device__ __nv_bfloat16 g_h1hi[(size_t)BATCH * NVERT * 32];
__device__ __nv_bfloat16 g_h1lo[(size_t)BATCH * NVERT * 32];
__device__ __nv_bfloat16 g_h2hi[(size_t)BATCH * NVERT * 64];
__device__ __nv_bfloat16 g_h2lo[(size_t)BATCH * NVERT * 64];
__device__ __nv_bfloat16 g_h3hi[(size_t)BATCH * NVERT * 128];
__device__ __nv_bfloat16 g_h3lo[(size_t)BATCH * NVERT * 128];
__device__ __nv_bfloat16 g_h4hi[(size_t)BATCH * NVERT * 128];
__device__ __nv_bfloat16 g_h4lo[(size_t)BATCH * NVERT * 128];

__device__ float g_wt0[27 * 32];
__device__ __nv_bfloat16 g_w1hi[64 * 320],   g_w1lo[64 * 320];
__device__ __nv_bfloat16 g_w2hi[128 * 576],  g_w2lo[128 * 576];
__device__ __nv_bfloat16 g_w3hi[128 * 1152], g_w3lo[128 * 1152];
__device__ __nv_bfloat16 g_wlhi[256 * 128],  g_wllo[256 * 128];

// ---------------------------------------------------------------------------
// Prep kernels
// ---------------------------------------------------------------------------
__global__ void transpose_w(const float* __restrict__ W, float* __restrict__ Wt,
                            int K, int OC) {
    int t = blockIdx.x * blockDim.x + threadIdx.x;
    if (t < K * OC) {
        int k = t / OC, o = t - k * OC;
        Wt[t] = W[o * K + k];
    }
}
__global__ void wconv(const float* __restrict__ W,
                      __nv_bfloat16* __restrict__ hi, __nv_bfloat16* __restrict__ lo,
                      int K, int KPAD, int OC) {
    int t = blockIdx.x * blockDim.x + threadIdx.x;
    if (t >= OC * KPAD) return;
    int o = t / KPAD, k = t - o * KPAD;
    float w = (k < K) ? W[o * K + k] : 0.f;
    __nv_bfloat16 h = __float2bfloat16(w);
    hi[t] = h;
    lo[t] = __float2bfloat16(w - __bfloat162float(h));
}

// ---------------------------------------------------------------------------
// Layer 0 (SIMT fp32, tiny): 3 -> 32, emits hi/lo bf16 planes
// ---------------------------------------------------------------------------
__global__ void __launch_bounds__(128)
layer0_kernel(const float* __restrict__ x,
              const int*   __restrict__ sidx_g,
              const float* __restrict__ Wt,
              const float* __restrict__ bias,
              __nv_bfloat16* __restrict__ hout_hi,
              __nv_bfloat16* __restrict__ hout_lo) {
    constexpr int IN_C = 3, OUT_C = 32, KC = 27, ROWS = 128, TM = 8, TN = 4;
    constexpr int TX = OUT_C / TN;
    constexpr int NT = 128;
    constexpr int AS = KC + 1;

    extern __shared__ __align__(1024) char dsm[];
    float* Asm = (float*)dsm;
    float* Wsm = Asm + ROWS * AS;
    int*   sidx = (int*)(Wsm + KC * OUT_C);

    const int tid = threadIdx.x;
    const int tx = tid % TX, ty = tid / TX;
    const int v0 = blockIdx.x * 4;

    if (tid < 36) {
        int vt = tid / SP, s = tid - vt * SP;
        int v = v0 + vt; if (v >= NVERT) v = NVERT - 1;
        sidx[tid] = sidx_g[v * SP + s];
    }
    for (int t = tid; t < KC * OUT_C; t += NT) Wsm[t] = Wt[t];
    __syncthreads();
    for (int t = tid; t < ROWS * KC; t += NT) {
        int r = t / KC, kk = t - r * KC;
        int vt = r >> 5, b = r & 31;
        int s = kk / IN_C, c = kk - s * IN_C;
        int srow = sidx[vt * SP + s];
        Asm[r * AS + kk] = x[((size_t)b * NVERT + srow) * IN_C + c];
    }
    __syncthreads();

    float acc[TM][TN];
#pragma unroll
    for (int i = 0; i < TM; ++i)
#pragma unroll
        for (int j = 0; j < TN; ++j) acc[i][j] = 0.f;

#pragma unroll
    for (int k = 0; k < KC; ++k) {
        float a[TM];
#pragma unroll
        for (int i = 0; i < TM; ++i) a[i] = Asm[(ty * TM + i) * AS + k];
        float4 wv = *(const float4*)(Wsm + k * OUT_C + tx * TN);
        float w[TN] = {wv.x, wv.y, wv.z, wv.w};
#pragma unroll
        for (int i = 0; i < TM; ++i)
#pragma unroll
            for (int j = 0; j < TN; ++j) acc[i][j] += a[i] * w[j];
    }

#pragma unroll
    for (int i = 0; i < TM; ++i) {
        int r = ty * TM + i;
        int vt = r >> 5, b = r & 31;
        int v = v0 + vt;
        if (v < NVERT) {
            size_t off = ((size_t)b * NVERT + v) * OUT_C + tx * TN;
#pragma unroll
            for (int j = 0; j < TN; ++j) {
                float y = acc[i][j] + __ldg(&bias[tx * TN + j]);
                __nv_bfloat16 h = __float2bfloat16(y);
                hout_hi[off + j] = h;
                hout_lo[off + j] = __float2bfloat16(y - __bfloat162float(h));
            }
        }
    }
}

// ---------------------------------------------------------------------------
// HMMA bf16-split layer.
//   Block tile: MROWS (=MV*32) rows x OUT_C cols; K chunked at 64, cp.async
//   double-buffered. Warp grid WRG x WCG; warp tile (MROWS/WRG) x (OUT_C/WCG).
//   3 MMA passes per k16: AhiBhi + AhiBlo + AloBhi, fp32 accumulators.
// ---------------------------------------------------------------------------
template<int IN_C, int OUT_C, int KREAL, int KPAD, int MV, int WRG, int WCG,
         bool GATHER, bool FINAL>
__global__ void __launch_bounds__(256, 1)
mma_layer(const __nv_bfloat16* __restrict__ hin_hi,
          const __nv_bfloat16* __restrict__ hin_lo,
          const int*           __restrict__ sidx_g,
          const __nv_bfloat16* __restrict__ whi,
          const __nv_bfloat16* __restrict__ wlo,
          const float*         __restrict__ bias,
          __nv_bfloat16*       __restrict__ hout_hi,
          __nv_bfloat16*       __restrict__ hout_lo,
          float*               __restrict__ fout) {
    constexpr int MROWS = MV * 32;
    constexpr int NCH   = KPAD / 64;
    constexpr int ATB   = MROWS * 128;      // bytes per A plane-buffer
    constexpr int BTB   = OUT_C * 128;      // bytes per B plane-buffer
    constexpr int SM_A  = 2048;
    constexpr int SM_B  = SM_A + 4 * ATB;
    constexpr int WARP_R = MROWS / WRG;
    constexpr int WARP_C = OUT_C / WCG;
    constexpr int RS = WARP_R / 16;
    constexpr int NO = WARP_C / 8;
    constexpr int TOT_A = MROWS * 8 * 2;    // 16B-group tasks per chunk (2 planes)
    constexpr int TOT_B = OUT_C * 8 * 2;

    extern __shared__ __align__(1024) char dsm[];
    const uint32_t sbase = smem_u32(dsm);
    int*   sidx = (int*)dsm;                // MV*9 ints
    float* bsm  = (float*)(dsm + 256);      // OUT_C floats

    const int tid  = threadIdx.x;
    const int wid  = tid >> 5;
    const int lane = tid & 31;
    const int v0   = blockIdx.x * MV;

    const int wr = wid % WRG, wc = wid / WRG;
    const int warp_r0 = wr * WARP_R;
    const int warp_c0 = wc * WARP_C;

    if (GATHER && tid < MV * SP) {
        int vt = tid / SP, s = tid - vt * SP;
        int v = v0 + vt; if (v >= NVERT) v = NVERT - 1;
        sidx[tid] = sidx_g[v * SP + s];
    }
    for (int t = tid; t < OUT_C; t += 256) bsm[t] = bias[t];
    __syncthreads();

    // ---- chunk loader: gather A + stream B into buffer `buf` ----
    auto load_chunk = [&](int ch, int buf) {
        // A: 16B per task; task = plane * (MROWS*8) + r*8 + g
#pragma unroll
        for (int t = tid; t < TOT_A; t += 256) {
            int plane = t >= MROWS * 8;
            int rg = plane ? t - MROWS * 8 : t;
            int r = rg >> 3, g = rg & 7;
            int vt = r >> 5, b = r & 31;
            int kg = ch * 64 + g * 8;
            int kgc = kg < KREAL ? kg : (KREAL - 1);
            int s = GATHER ? kgc / IN_C : 0;
            int c = GATHER ? kgc - s * IN_C : kgc;
            int v = v0 + vt; if (v >= NVERT) v = NVERT - 1;
            int srow = GATHER ? sidx[vt * SP + s] : v;
            const __nv_bfloat16* src = (plane ? hin_lo : hin_hi)
                + ((size_t)b * NVERT + srow) * IN_C + c;
            uint32_t dst = sbase + SM_A + (uint32_t)(buf * 2 + plane) * ATB
                         + swz((uint32_t)(r * 128 + g * 16));
            cp16(dst, src, kg < KREAL ? 16 : 0);
        }
        // B
#pragma unroll
        for (int t = tid; t < TOT_B; t += 256) {
            int plane = t >= OUT_C * 8;
            int rg = plane ? t - OUT_C * 8 : t;
            int n = rg >> 3, g = rg & 7;
            int kg = ch * 64 + g * 8;
            const __nv_bfloat16* src = (plane ? wlo : whi) + (size_t)n * KPAD + kg;
            uint32_t dst = sbase + SM_B + (uint32_t)(buf * 2 + plane) * BTB
                         + swz((uint32_t)(n * 128 + g * 16));
            cp16(dst, src, 16);
        }
        cp_commit();
    };

    float acc[RS][NO][4];
#pragma unroll
    for (int i = 0; i < RS; ++i)
#pragma unroll
        for (int j = 0; j < NO; ++j)
#pragma unroll
            for (int q = 0; q < 4; ++q) acc[i][j][q] = 0.f;

    const int grp = lane >> 3, lr = lane & 7;

    load_chunk(0, 0);

    for (int ch = 0; ch < NCH; ++ch) {
        const int buf = ch & 1;
        if (ch + 1 < NCH) { load_chunk(ch + 1, buf ^ 1); cp_wait1(); }
        else              { cp_wait0(); }
        __syncthreads();

        const uint32_t Ahi = sbase + SM_A + (uint32_t)(buf * 2 + 0) * ATB;
        const uint32_t Alo = sbase + SM_A + (uint32_t)(buf * 2 + 1) * ATB;
        const uint32_t Bhi = sbase + SM_B + (uint32_t)(buf * 2 + 0) * BTB;
        const uint32_t Blo = sbase + SM_B + (uint32_t)(buf * 2 + 1) * BTB;

#pragma unroll
        for (int ks = 0; ks < 4; ++ks) {
            // B fragments for this k16: NO octs, hi+lo planes
            uint32_t bh[NO][2], bl_[NO][2];
#pragma unroll
            for (int p16 = 0; p16 < NO / 2; ++p16) {
                int n  = warp_c0 + p16 * 16 + (grp >> 1) * 8 + lr;
                int kb = ks * 2 + (grp & 1);
                uint32_t off = swz((uint32_t)(n * 128 + kb * 16));
                uint32_t m[4];
                ldm4(Bhi + off, m);
                bh[2 * p16][0] = m[0]; bh[2 * p16][1] = m[1];
                bh[2 * p16 + 1][0] = m[2]; bh[2 * p16 + 1][1] = m[3];
                ldm4(Blo + off, m);
                bl_[2 * p16][0] = m[0]; bl_[2 * p16][1] = m[1];
                bl_[2 * p16 + 1][0] = m[2]; bl_[2 * p16 + 1][1] = m[3];
            }
#pragma unroll
            for (int sub = 0; sub < RS; ++sub) {
                int row = warp_r0 + sub * 16 + (grp & 1) * 8 + lr;
                int kb  = ks * 2 + (grp >> 1);
                uint32_t off = swz((uint32_t)(row * 128 + kb * 16));
                uint32_t ah[4], al[4];
                ldm4(Ahi + off, ah);
                ldm4(Alo + off, al);
#pragma unroll
                for (int oct = 0; oct < NO; ++oct) {
                    mma16816(acc[sub][oct], ah, bh[oct]);
                    mma16816(acc[sub][oct], ah, bl_[oct]);
                    mma16816(acc[sub][oct], al, bh[oct]);
                }
            }
        }
        __syncthreads();
    }

    // ---- epilogue: bias + (re-split | f32) stores straight from D frags ----
    const int tq = lane >> 2, tr = lane & 3;
#pragma unroll
    for (int sub = 0; sub < RS; ++sub) {
#pragma unroll
        for (int half = 0; half < 2; ++half) {
            int r = warp_r0 + sub * 16 + half * 8 + tq;
            int vt = r >> 5, b = r & 31;
            int v = v0 + vt;
            if (v >= NVERT) continue;
#pragma unroll
            for (int oct = 0; oct < NO; ++oct) {
                int col = warp_c0 + oct * 8 + tr * 2;
                float y0 = acc[sub][oct][2 * half]     + bsm[col];
                float y1 = acc[sub][oct][2 * half + 1] + bsm[col + 1];
                size_t base = ((size_t)b * NVERT + v) * OUT_C + col;
                if (FINAL) {
                    *(float2*)(fout + base) = make_float2(y0, y1);
                } else {
                    __nv_bfloat16 h0 = __float2bfloat16(y0);
                    __nv_bfloat16 h1 = __float2bfloat16(y1);
                    __nv_bfloat162 hp; hp.x = h0; hp.y = h1;
                    __nv_bfloat162 lp;
                    lp.x = __float2bfloat16(y0 - __bfloat162float(h0));
                    lp.y = __float2bfloat16(y1 - __bfloat162float(h1));
                    *(uint32_t*)(hout_hi + base) = *reinterpret_cast<uint32_t*>(&hp);
                    *(uint32_t*)(hout_lo + base) = *reinterpret_cast<uint32_t*>(&lp);
                }
            }
        }
    }
}

// ---------------------------------------------------------------------------
// Host
// ---------------------------------------------------------------------------
extern "C" void kernel_launch(void* const* d_in, const int* in_sizes, int n_in,
                              void* d_out, int out_size) {
    const float* x  = (const float*)d_in[0];
    const int*   sp = (const int*)  d_in[1];
    const float* W0 = (const float*)d_in[2];
    const float* b0 = (const float*)d_in[3];
    const float* W1 = (const float*)d_in[4];
    const float* b1 = (const float*)d_in[5];
    const float* W2 = (const float*)d_in[6];
    const float* b2 = (const float*)d_in[7];
    const float* W3 = (const float*)d_in[8];
    const float* b3 = (const float*)d_in[9];
    const float* Wl = (const float*)d_in[10];
    const float* bl = (const float*)d_in[11];
    float* out = (float*)d_out;

    __nv_bfloat16 *h1hi, *h1lo, *h2hi, *h2lo, *h3hi, *h3lo, *h4hi, *h4lo;
    __nv_bfloat16 *w1hi, *w1lo, *w2hi, *w2lo, *w3hi, *w3lo, *wlhi, *wllo;
    float *wt0;
    cudaGetSymbolAddress((void**)&h1hi, g_h1hi);  cudaGetSymbolAddress((void**)&h1lo, g_h1lo);
    cudaGetSymbolAddress((void**)&h2hi, g_h2hi);  cudaGetSymbolAddress((void**)&h2lo, g_h2lo);
    cudaGetSymbolAddress((void**)&h3hi, g_h3hi);  cudaGetSymbolAddress((void**)&h3lo, g_h3lo);
    cudaGetSymbolAddress((void**)&h4hi, g_h4hi);  cudaGetSymbolAddress((void**)&h4lo, g_h4lo);
    cudaGetSymbolAddress((void**)&w1hi, g_w1hi);  cudaGetSymbolAddress((void**)&w1lo, g_w1lo);
    cudaGetSymbolAddress((void**)&w2hi, g_w2hi);  cudaGetSymbolAddress((void**)&w2lo, g_w2lo);
    cudaGetSymbolAddress((void**)&w3hi, g_w3hi);  cudaGetSymbolAddress((void**)&w3lo, g_w3lo);
    cudaGetSymbolAddress((void**)&wlhi, g_wlhi);  cudaGetSymbolAddress((void**)&wllo, g_wllo);
    cudaGetSymbolAddress((void**)&wt0,  g_wt0);

    transpose_w<<<(27 * 32 + 255) / 256, 256>>>(W0, wt0, 27, 32);
    wconv<<<(64  * 320  + 255) / 256, 256>>>(W1, w1hi, w1lo, 288,  320,  64);
    wconv<<<(128 * 576  + 255) / 256, 256>>>(W2, w2hi, w2lo, 576,  576,  128);
    wconv<<<(128 * 1152 + 255) / 256, 256>>>(W3, w3hi, w3lo, 1152, 1152, 128);
    wconv<<<(256 * 128  + 255) / 256, 256>>>(Wl, wlhi, wllo, 128,  128,  256);

    const int* sp0 = sp + 0 * NVERT * SP;
    const int* sp1 = sp + 1 * NVERT * SP;
    const int* sp2 = sp + 2 * NVERT * SP;
    const int* sp3 = sp + 3 * NVERT * SP;

    const int grid4 = (NVERT + 3) / 4;   // 1256
    const int grid2 = (NVERT + 1) / 2;   // 2512

    // ---- Layer 0 (SIMT) ----
    {
        constexpr int smb = (128 * 28 + 27 * 32) * 4 + 64 * 4;
        layer0_kernel<<<grid4, 128, smb>>>(x, sp0, wt0, b0, h1hi, h1lo);
    }
    // ---- Layer 1: 32 -> 64, K=288 (pad 320) ----
    {
        auto k = mma_layer<32, 64, 288, 320, 4, 4, 2, true, false>;
        constexpr int smb = 2048 + 4 * 128 * 128 + 4 * 64 * 128;   // 100352
        cudaFuncSetAttribute((const void*)k, cudaFuncAttributeMaxDynamicSharedMemorySize, smb);
        k<<<grid4, 256, smb>>>(h1hi, h1lo, sp1, w1hi, w1lo, b1, h2hi, h2lo, nullptr);
    }
    // ---- Layer 2: 64 -> 128, K=576 ----
    {
        auto k = mma_layer<64, 128, 576, 576, 4, 2, 4, true, false>;
        constexpr int smb = 2048 + 4 * 128 * 128 + 4 * 128 * 128;  // 133120
        cudaFuncSetAttribute((const void*)k, cudaFuncAttributeMaxDynamicSharedMemorySize, smb);
        k<<<grid4, 256, smb>>>(h2hi, h2lo, sp2, w2hi, w2lo, b2, h3hi, h3lo, nullptr);
    }
    // ---- Layer 3: 128 -> 128, K=1152 ----
    {
        auto k = mma_layer<128, 128, 1152, 1152, 4, 2, 4, true, false>;
        constexpr int smb = 2048 + 4 * 128 * 128 + 4 * 128 * 128;  // 133120
        cudaFuncSetAttribute((const void*)k, cudaFuncAttributeMaxDynamicSharedMemorySize, smb);
        k<<<grid4, 256, smb>>>(h3hi, h3lo, sp3, w3hi, w3lo, b3, h4hi, h4lo, nullptr);
    }
    // ---- Final: 128 -> 256, no gather, M=64/block ----
    {
        auto k = mma_layer<128, 256, 128, 128, 2, 2, 4, false, true>;
        constexpr int smb = 2048 + 4 * 64 * 128 + 4 * 256 * 128;   // 165888
        cudaFuncSetAttribute((const void*)k, cudaFuncAttributeMaxDynamicSharedMemorySize, smb);
        k<<<grid2, 256, smb>>>(h4hi, h4lo, nullptr, wlhi, wllo, bl, nullptr, nullptr, out);
    }
}

// round 5
// speedup vs baseline: 2.8375x; 1.0543x over previous
#include <cuda_runtime.h>
#include <cuda_bf16.h>
#include <cstdint>
#include <cstddef>

static constexpr int BATCH = 32;
static constexpr int NVERT = 5023;
static constexpr int SP    = 9;

// ---------------------------------------------------------------------------
// Helpers (sm_100 base target: mma.sync + ldmatrix + cp.async only)
// ---------------------------------------------------------------------------
__device__ __forceinline__ uint32_t smem_u32(const void* p) {
    uint32_t a;
    asm("{ .reg .u64 t; cvta.to.shared.u64 t, %1; cvt.u32.u64 %0, t; }" : "=r"(a) : "l"(p));
    return a;
}
__device__ __forceinline__ void cp16(uint32_t dst, const void* src, int srcbytes) {
    asm volatile("cp.async.ca.shared.global [%0], [%1], 16, %2;"
                 :: "r"(dst), "l"(src), "r"(srcbytes));
}
__device__ __forceinline__ void cp_commit() {
    asm volatile("cp.async.commit_group;" ::: "memory");
}
__device__ __forceinline__ void cp_wait0() {
    asm volatile("cp.async.wait_group 0;" ::: "memory");
}
__device__ __forceinline__ void cp_wait1() {
    asm volatile("cp.async.wait_group 1;" ::: "memory");
}
__device__ __forceinline__ void ldm4(uint32_t addr, uint32_t* r) {
    asm volatile("ldmatrix.sync.aligned.m8n8.x4.shared.b16 {%0,%1,%2,%3}, [%4];"
                 : "=r"(r[0]), "=r"(r[1]), "=r"(r[2]), "=r"(r[3]) : "r"(addr));
}
__device__ __forceinline__ void mma16816(float* d, const uint32_t* a, const uint32_t* b) {
    asm volatile("mma.sync.aligned.m16n8k16.row.col.f32.bf16.bf16.f32 "
                 "{%0,%1,%2,%3}, {%4,%5,%6,%7}, {%8,%9}, {%0,%1,%2,%3};"
                 : "+f"(d[0]), "+f"(d[1]), "+f"(d[2]), "+f"(d[3])
                 : "r"(a[0]), "r"(a[1]), "r"(a[2]), "r"(a[3]), "r"(b[0]), "r"(b[1]));
}
// SW64 swizzle for 64-byte rows (8 rows x 64B atom = 512B)
__device__ __forceinline__ uint32_t swz64(uint32_t off) { return off ^ ((off >> 3) & 0x30); }

// ---------------------------------------------------------------------------
// Device global scratch
// ---------------------------------------------------------------------------
__device__ __nv_bfloat16 g_h1hi[(size_t)BATCH * NVERT * 32];
__device__ __nv_bfloat16 g_h1lo[(size_t)BATCH * NVERT * 32];
__device__ __nv_bfloat16 g_h2hi[(size_t)BATCH * NVERT * 64];
__device__ __nv_bfloat16 g_h2lo[(size_t)BATCH * NVERT * 64];
__device__ __nv_bfloat16 g_h3hi[(size_t)BATCH * NVERT * 128];
__device__ __nv_bfloat16 g_h3lo[(size_t)BATCH * NVERT * 128];
__device__ __nv_bfloat16 g_h4hi[(size_t)BATCH * NVERT * 128];
__device__ __nv_bfloat16 g_h4lo[(size_t)BATCH * NVERT * 128];

__device__ float g_wt0[27 * 32];
__device__ __nv_bfloat16 g_w1hi[64 * 320],   g_w1lo[64 * 320];
__device__ __nv_bfloat16 g_w2hi[128 * 576],  g_w2lo[128 * 576];
__device__ __nv_bfloat16 g_w3hi[128 * 1152], g_w3lo[128 * 1152];
__device__ __nv_bfloat16 g_wlhi[256 * 128],  g_wllo[256 * 128];

// ---------------------------------------------------------------------------
// Single fused weight-prep kernel (transpose W0 + hi/lo split W1..W3, Wl)
// ---------------------------------------------------------------------------
struct WJob { const float* W; __nv_bfloat16* hi; __nv_bfloat16* lo; int K, KPAD, OC; };

__global__ void prep_weights(const float* W0, float* wt0,
                             const float* W1, __nv_bfloat16* w1hi, __nv_bfloat16* w1lo,
                             const float* W2, __nv_bfloat16* w2hi, __nv_bfloat16* w2lo,
                             const float* W3, __nv_bfloat16* w3hi, __nv_bfloat16* w3lo,
                             const float* Wl, __nv_bfloat16* wlhi, __nv_bfloat16* wllo) {
    int t = blockIdx.x * blockDim.x + threadIdx.x;
    // range 0: W0 transpose (864)
    if (t < 864) {
        int k = t / 32, o = t - k * 32;
        wt0[t] = W0[o * 27 + k];
        return;
    }
    t -= 864;
    const float* W; __nv_bfloat16* hi; __nv_bfloat16* lo; int K, KPAD, OC;
    if (t < 64 * 320)            { W = W1; hi = w1hi; lo = w1lo; K = 288;  KPAD = 320;  OC = 64; }
    else if ((t -= 64 * 320)  < 128 * 576)  { W = W2; hi = w2hi; lo = w2lo; K = 576;  KPAD = 576;  OC = 128; }
    else if ((t -= 128 * 576) < 128 * 1152) { W = W3; hi = w3hi; lo = w3lo; K = 1152; KPAD = 1152; OC = 128; }
    else if ((t -= 128 * 1152) < 256 * 128) { W = Wl; hi = wlhi; lo = wllo; K = 128;  KPAD = 128;  OC = 256; }
    else return;
    int o = t / KPAD, k = t - o * KPAD;
    float w = (k < K) ? W[o * K + k] : 0.f;
    __nv_bfloat16 h = __float2bfloat16(w);
    hi[t] = h;
    lo[t] = __float2bfloat16(w - __bfloat162float(h));
}

// ---------------------------------------------------------------------------
// Layer 0 (SIMT fp32, tiny): 3 -> 32, emits hi/lo bf16 planes
// ---------------------------------------------------------------------------
__global__ void __launch_bounds__(128)
layer0_kernel(const float* __restrict__ x,
              const int*   __restrict__ sidx_g,
              const float* __restrict__ Wt,
              const float* __restrict__ bias,
              __nv_bfloat16* __restrict__ hout_hi,
              __nv_bfloat16* __restrict__ hout_lo) {
    constexpr int IN_C = 3, OUT_C = 32, KC = 27, ROWS = 128, TM = 8, TN = 4;
    constexpr int TX = OUT_C / TN;
    constexpr int NT = 128;
    constexpr int AS = KC + 1;

    extern __shared__ __align__(1024) char dsm[];
    float* Asm = (float*)dsm;
    float* Wsm = Asm + ROWS * AS;
    int*   sidx = (int*)(Wsm + KC * OUT_C);

    const int tid = threadIdx.x;
    const int tx = tid % TX, ty = tid / TX;
    const int v0 = blockIdx.x * 4;

    if (tid < 36) {
        int vt = tid / SP, s = tid - vt * SP;
        int v = v0 + vt; if (v >= NVERT) v = NVERT - 1;
        sidx[tid] = sidx_g[v * SP + s];
    }
    for (int t = tid; t < KC * OUT_C; t += NT) Wsm[t] = Wt[t];
    __syncthreads();
    for (int t = tid; t < ROWS * KC; t += NT) {
        int r = t / KC, kk = t - r * KC;
        int vt = r >> 5, b = r & 31;
        int s = kk / IN_C, c = kk - s * IN_C;
        int srow = sidx[vt * SP + s];
        Asm[r * AS + kk] = x[((size_t)b * NVERT + srow) * IN_C + c];
    }
    __syncthreads();

    float acc[TM][TN];
#pragma unroll
    for (int i = 0; i < TM; ++i)
#pragma unroll
        for (int j = 0; j < TN; ++j) acc[i][j] = 0.f;

#pragma unroll
    for (int k = 0; k < KC; ++k) {
        float a[TM];
#pragma unroll
        for (int i = 0; i < TM; ++i) a[i] = Asm[(ty * TM + i) * AS + k];
        float4 wv = *(const float4*)(Wsm + k * OUT_C + tx * TN);
        float w[TN] = {wv.x, wv.y, wv.z, wv.w};
#pragma unroll
        for (int i = 0; i < TM; ++i)
#pragma unroll
            for (int j = 0; j < TN; ++j) acc[i][j] += a[i] * w[j];
    }

#pragma unroll
    for (int i = 0; i < TM; ++i) {
        int r = ty * TM + i;
        int vt = r >> 5, b = r & 31;
        int v = v0 + vt;
        if (v < NVERT) {
            size_t off = ((size_t)b * NVERT + v) * OUT_C + tx * TN;
#pragma unroll
            for (int j = 0; j < TN; ++j) {
                float y = acc[i][j] + __ldg(&bias[tx * TN + j]);
                __nv_bfloat16 h = __float2bfloat16(y);
                hout_hi[off + j] = h;
                hout_lo[off + j] = __float2bfloat16(y - __bfloat162float(h));
            }
        }
    }
}

// ---------------------------------------------------------------------------
// HMMA bf16-split layer, KC=32 (64-byte smem rows, SW64 swizzle).
//   Block tile: MROWS (=MV*32) x OUT_C; K chunked at 32, cp.async double-buffered.
//   3 MMA passes per k16: AhiBhi + AhiBlo + AloBhi, fp32 accumulators.
//   smem halved vs KC=64 -> 2 CTAs/SM.
// ---------------------------------------------------------------------------
template<int IN_C, int OUT_C, int KREAL, int KPAD, int MV, int WRG, int WCG,
         bool GATHER, bool FINAL>
__global__ void __launch_bounds__(256, 2)
mma_layer(const __nv_bfloat16* __restrict__ hin_hi,
          const __nv_bfloat16* __restrict__ hin_lo,
          const int*           __restrict__ sidx_g,
          const __nv_bfloat16* __restrict__ whi,
          const __nv_bfloat16* __restrict__ wlo,
          const float*         __restrict__ bias,
          __nv_bfloat16*       __restrict__ hout_hi,
          __nv_bfloat16*       __restrict__ hout_lo,
          float*               __restrict__ fout) {
    constexpr int MROWS = MV * 32;
    constexpr int NCH   = KPAD / 32;
    constexpr int ATB   = MROWS * 64;       // bytes per A plane-buffer (64B rows)
    constexpr int BTB   = OUT_C * 64;       // bytes per B plane-buffer
    constexpr int SM_A  = 2048;
    constexpr int SM_B  = SM_A + 4 * ATB;
    constexpr int WARP_R = MROWS / WRG;
    constexpr int WARP_C = OUT_C / WCG;
    constexpr int RS = WARP_R / 16;
    constexpr int NO = WARP_C / 8;
    constexpr int TOT_A = MROWS * 4 * 2;    // 16B tasks per chunk (4 units/row, 2 planes)
    constexpr int TOT_B = OUT_C * 4 * 2;

    extern __shared__ __align__(1024) char dsm[];
    const uint32_t sbase = smem_u32(dsm);
    int*   sidx = (int*)dsm;                // MV*9 ints
    float* bsm  = (float*)(dsm + 256);      // OUT_C floats

    const int tid  = threadIdx.x;
    const int wid  = tid >> 5;
    const int lane = tid & 31;
    const int v0   = blockIdx.x * MV;

    const int wr = wid % WRG, wc = wid / WRG;
    const int warp_r0 = wr * WARP_R;
    const int warp_c0 = wc * WARP_C;

    if (GATHER && tid < MV * SP) {
        int vt = tid / SP, s = tid - vt * SP;
        int v = v0 + vt; if (v >= NVERT) v = NVERT - 1;
        sidx[tid] = sidx_g[v * SP + s];
    }
    for (int t = tid; t < OUT_C; t += 256) bsm[t] = bias[t];
    __syncthreads();

    // ---- chunk loader: gather A + stream B into buffer `buf` ----
    auto load_chunk = [&](int ch, int buf) {
#pragma unroll
        for (int t = tid; t < TOT_A; t += 256) {
            int plane = t >= MROWS * 4;
            int rg = plane ? t - MROWS * 4 : t;
            int r = rg >> 2, g = rg & 3;
            int vt = r >> 5, b = r & 31;
            int kg = ch * 32 + g * 8;
            int kgc = kg < KREAL ? kg : 0;
            int s = GATHER ? kgc / IN_C : 0;
            int c = GATHER ? kgc - s * IN_C : kgc;
            int v = v0 + vt; if (v >= NVERT) v = NVERT - 1;
            int srow = GATHER ? sidx[vt * SP + s] : v;
            const __nv_bfloat16* src = (plane ? hin_lo : hin_hi)
                + ((size_t)b * NVERT + srow) * IN_C + c;
            uint32_t dst = sbase + SM_A + (uint32_t)(buf * 2 + plane) * ATB
                         + swz64((uint32_t)(r * 64 + g * 16));
            cp16(dst, src, kg < KREAL ? 16 : 0);
        }
#pragma unroll
        for (int t = tid; t < TOT_B; t += 256) {
            int plane = t >= OUT_C * 4;
            int rg = plane ? t - OUT_C * 4 : t;
            int n = rg >> 2, g = rg & 3;
            int kg = ch * 32 + g * 8;
            const __nv_bfloat16* src = (plane ? wlo : whi) + (size_t)n * KPAD + kg;
            uint32_t dst = sbase + SM_B + (uint32_t)(buf * 2 + plane) * BTB
                         + swz64((uint32_t)(n * 64 + g * 16));
            cp16(dst, src, 16);
        }
        cp_commit();
    };

    float acc[RS][NO][4];
#pragma unroll
    for (int i = 0; i < RS; ++i)
#pragma unroll
        for (int j = 0; j < NO; ++j)
#pragma unroll
            for (int q = 0; q < 4; ++q) acc[i][j][q] = 0.f;

    const int grp = lane >> 3, lr = lane & 7;

    load_chunk(0, 0);

    for (int ch = 0; ch < NCH; ++ch) {
        const int buf = ch & 1;
        if (ch + 1 < NCH) { load_chunk(ch + 1, buf ^ 1); cp_wait1(); }
        else              { cp_wait0(); }
        __syncthreads();

        const uint32_t Ahi = sbase + SM_A + (uint32_t)(buf * 2 + 0) * ATB;
        const uint32_t Alo = sbase + SM_A + (uint32_t)(buf * 2 + 1) * ATB;
        const uint32_t Bhi = sbase + SM_B + (uint32_t)(buf * 2 + 0) * BTB;
        const uint32_t Blo = sbase + SM_B + (uint32_t)(buf * 2 + 1) * BTB;

#pragma unroll
        for (int ks = 0; ks < 2; ++ks) {            // 2 k16 steps per KC=32 chunk
            uint32_t bh[NO][2], bl_[NO][2];
#pragma unroll
            for (int p16 = 0; p16 < NO / 2; ++p16) {
                int n  = warp_c0 + p16 * 16 + (grp >> 1) * 8 + lr;
                int c16 = ks * 2 + (grp & 1);       // 16B column 0..3
                uint32_t off = swz64((uint32_t)(n * 64 + c16 * 16));
                uint32_t m[4];
                ldm4(Bhi + off, m);
                bh[2 * p16][0] = m[0]; bh[2 * p16][1] = m[1];
                bh[2 * p16 + 1][0] = m[2]; bh[2 * p16 + 1][1] = m[3];
                ldm4(Blo + off, m);
                bl_[2 * p16][0] = m[0]; bl_[2 * p16][1] = m[1];
                bl_[2 * p16 + 1][0] = m[2]; bl_[2 * p16 + 1][1] = m[3];
            }
#pragma unroll
            for (int sub = 0; sub < RS; ++sub) {
                int row = warp_r0 + sub * 16 + (grp & 1) * 8 + lr;
                int c16 = ks * 2 + (grp >> 1);
                uint32_t off = swz64((uint32_t)(row * 64 + c16 * 16));
                uint32_t ah[4], al[4];
                ldm4(Ahi + off, ah);
                ldm4(Alo + off, al);
#pragma unroll
                for (int oct = 0; oct < NO; ++oct) {
                    mma16816(acc[sub][oct], ah, bh[oct]);
                    mma16816(acc[sub][oct], ah, bl_[oct]);
                    mma16816(acc[sub][oct], al, bh[oct]);
                }
            }
        }
        __syncthreads();
    }

    // ---- epilogue: bias + (re-split | f32) stores straight from D frags ----
    const int tq = lane >> 2, tr = lane & 3;
#pragma unroll
    for (int sub = 0; sub < RS; ++sub) {
#pragma unroll
        for (int half = 0; half < 2; ++half) {
            int r = warp_r0 + sub * 16 + half * 8 + tq;
            int vt = r >> 5, b = r & 31;
            int v = v0 + vt;
            if (v >= NVERT) continue;
#pragma unroll
            for (int oct = 0; oct < NO; ++oct) {
                int col = warp_c0 + oct * 8 + tr * 2;
                float y0 = acc[sub][oct][2 * half]     + bsm[col];
                float y1 = acc[sub][oct][2 * half + 1] + bsm[col + 1];
                size_t base = ((size_t)b * NVERT + v) * OUT_C + col;
                if (FINAL) {
                    *(float2*)(fout + base) = make_float2(y0, y1);
                } else {
                    __nv_bfloat16 h0 = __float2bfloat16(y0);
                    __nv_bfloat16 h1 = __float2bfloat16(y1);
                    __nv_bfloat162 hp; hp.x = h0; hp.y = h1;
                    __nv_bfloat162 lp;
                    lp.x = __float2bfloat16(y0 - __bfloat162float(h0));
                    lp.y = __float2bfloat16(y1 - __bfloat162float(h1));
                    *(uint32_t*)(hout_hi + base) = *reinterpret_cast<uint32_t*>(&hp);
                    *(uint32_t*)(hout_lo + base) = *reinterpret_cast<uint32_t*>(&lp);
                }
            }
        }
    }
}

// ---------------------------------------------------------------------------
// Host
// ---------------------------------------------------------------------------
extern "C" void kernel_launch(void* const* d_in, const int* in_sizes, int n_in,
                              void* d_out, int out_size) {
    const float* x  = (const float*)d_in[0];
    const int*   sp = (const int*)  d_in[1];
    const float* W0 = (const float*)d_in[2];
    const float* b0 = (const float*)d_in[3];
    const float* W1 = (const float*)d_in[4];
    const float* b1 = (const float*)d_in[5];
    const float* W2 = (const float*)d_in[6];
    const float* b2 = (const float*)d_in[7];
    const float* W3 = (const float*)d_in[8];
    const float* b3 = (const float*)d_in[9];
    const float* Wl = (const float*)d_in[10];
    const float* bl = (const float*)d_in[11];
    float* out = (float*)d_out;

    __nv_bfloat16 *h1hi, *h1lo, *h2hi, *h2lo, *h3hi, *h3lo, *h4hi, *h4lo;
    __nv_bfloat16 *w1hi, *w1lo, *w2hi, *w2lo, *w3hi, *w3lo, *wlhi, *wllo;
    float *wt0;
    cudaGetSymbolAddress((void**)&h1hi, g_h1hi);  cudaGetSymbolAddress((void**)&h1lo, g_h1lo);
    cudaGetSymbolAddress((void**)&h2hi, g_h2hi);  cudaGetSymbolAddress((void**)&h2lo, g_h2lo);
    cudaGetSymbolAddress((void**)&h3hi, g_h3hi);  cudaGetSymbolAddress((void**)&h3lo, g_h3lo);
    cudaGetSymbolAddress((void**)&h4hi, g_h4hi);  cudaGetSymbolAddress((void**)&h4lo, g_h4lo);
    cudaGetSymbolAddress((void**)&w1hi, g_w1hi);  cudaGetSymbolAddress((void**)&w1lo, g_w1lo);
    cudaGetSymbolAddress((void**)&w2hi, g_w2hi);  cudaGetSymbolAddress((void**)&w2lo, g_w2lo);
    cudaGetSymbolAddress((void**)&w3hi, g_w3hi);  cudaGetSymbolAddress((void**)&w3lo, g_w3lo);
    cudaGetSymbolAddress((void**)&wlhi, g_wlhi);  cudaGetSymbolAddress((void**)&wllo, g_wllo);
    cudaGetSymbolAddress((void**)&wt0,  g_wt0);

    // ---- fused weight prep (1 launch) ----
    {
        const int total = 864 + 64 * 320 + 128 * 576 + 128 * 1152 + 256 * 128;
        prep_weights<<<(total + 255) / 256, 256>>>(W0, wt0, W1, w1hi, w1lo,
                                                   W2, w2hi, w2lo, W3, w3hi, w3lo,
                                                   Wl, wlhi, wllo);
    }

    const int* sp0 = sp + 0 * NVERT * SP;
    const int* sp1 = sp + 1 * NVERT * SP;
    const int* sp2 = sp + 2 * NVERT * SP;
    const int* sp3 = sp + 3 * NVERT * SP;

    const int grid4 = (NVERT + 3) / 4;   // 1256
    const int grid2 = (NVERT + 1) / 2;   // 2512

    // ---- Layer 0 (SIMT) ----
    {
        constexpr int smb = (128 * 28 + 27 * 32) * 4 + 64 * 4;
        layer0_kernel<<<grid4, 128, smb>>>(x, sp0, wt0, b0, h1hi, h1lo);
    }
    // ---- Layer 1: 32 -> 64, K=288 (pad 320) ----
    {
        auto k = mma_layer<32, 64, 288, 320, 4, 4, 2, true, false>;
        constexpr int smb = 2048 + 4 * (128 * 64) + 4 * (64 * 64);   // 51200
        cudaFuncSetAttribute((const void*)k, cudaFuncAttributeMaxDynamicSharedMemorySize, smb);
        k<<<grid4, 256, smb>>>(h1hi, h1lo, sp1, w1hi, w1lo, b1, h2hi, h2lo, nullptr);
    }
    // ---- Layer 2: 64 -> 128, K=576 ----
    {
        auto k = mma_layer<64, 128, 576, 576, 4, 2, 4, true, false>;
        constexpr int smb = 2048 + 4 * (128 * 64) + 4 * (128 * 64);  // 67584
        cudaFuncSetAttribute((const void*)k, cudaFuncAttributeMaxDynamicSharedMemorySize, smb);
        k<<<grid4, 256, smb>>>(h2hi, h2lo, sp2, w2hi, w2lo, b2, h3hi, h3lo, nullptr);
    }
    // ---- Layer 3: 128 -> 128, K=1152 ----
    {
        auto k = mma_layer<128, 128, 1152, 1152, 4, 2, 4, true, false>;
        constexpr int smb = 2048 + 4 * (128 * 64) + 4 * (128 * 64);  // 67584
        cudaFuncSetAttribute((const void*)k, cudaFuncAttributeMaxDynamicSharedMemorySize, smb);
        k<<<grid4, 256, smb>>>(h3hi, h3lo, sp3, w3hi, w3lo, b3, h4hi, h4lo, nullptr);
    }
    // ---- Final: 128 -> 256, no gather, M=64/block ----
    {
        auto k = mma_layer<128, 256, 128, 128, 2, 2, 4, false, true>;
        constexpr int smb = 2048 + 4 * (64 * 64) + 4 * (256 * 64);   // 83968
        cudaFuncSetAttribute((const void*)k, cudaFuncAttributeMaxDynamicSharedMemorySize, smb);
        k<<<grid2, 256, smb>>>(h4hi, h4lo, nullptr, wlhi, wllo, bl, nullptr, nullptr, out);
    }
}